// round 12
// baseline (speedup 1.0000x reference)
#include <cuda_runtime.h>
#include <cuda_bf16.h>
#include <math.h>
#include <stdint.h>

// Problem constants
#define Bq   64
#define Tq   256
#define Cq   2048
#define WEq  256
#define Hq   1024
#define G3q  3072
#define BK   16
#define NSPL 6
#define NBLK 144
#define SPT  4

typedef unsigned long long u64;

// ---------------- scratch (device globals) -----------------------------------
__device__ float d_X  [Tq * Bq * WEq];
__device__ float d_gi [(size_t)Tq * Bq * G3q];   // [t][b][n]
__device__ float d_H  [(Tq + 1) * Bq * Hq];      // [t][b][j]
__device__ float d_ghp[NSPL][Bq][G3q];           // [split][b][n]
__device__ float d_e  [Tq * Bq * Tq];
__device__ float d_ctx[(size_t)Tq * Bq * Hq];
__device__ int   d_words[Bq];
__device__ int   d_cnt[Tq / SPT];
// bf16 split operands for tensor-core logits GEMM
__device__ __nv_bfloat16 d_Ah[(size_t)Tq * Bq * 2048];
__device__ __nv_bfloat16 d_Al[(size_t)Tq * Bq * 2048];
__device__ __nv_bfloat16 d_Bh[(size_t)Cq * 2048];
__device__ __nv_bfloat16 d_Bl[(size_t)Cq * 2048];

// ---------------- f32x2 helpers ----------------------------------------------
__device__ __forceinline__ void ffma2(u64& d, u64 a, u64 b) {
    asm("fma.rn.f32x2 %0, %1, %2, %0;" : "+l"(d) : "l"(a), "l"(b));
}
__device__ __forceinline__ float2 u2f2(u64 v) {
    unsigned lo, hi;
    asm("mov.b64 {%0, %1}, %2;" : "=r"(lo), "=r"(hi) : "l"(v));
    return make_float2(__uint_as_float(lo), __uint_as_float(hi));
}
__device__ __forceinline__ u64 pack2(float x) {
    u64 r;
    asm("mov.b64 %0, {%1, %1};" : "=l"(r) : "f"(x));
    return r;
}

// ---------------- mma.sync helpers (legacy HMMA path; valid on sm_103) --------
__device__ __forceinline__ unsigned smem_u32(const void* p) {
    unsigned a;
    asm("{ .reg .u64 t; cvta.to.shared.u64 t, %1; cvt.u32.u64 %0, t; }"
        : "=r"(a) : "l"(p));
    return a;
}
__device__ __forceinline__ void ldsm4(unsigned& r0, unsigned& r1,
                                      unsigned& r2, unsigned& r3, unsigned addr) {
    asm volatile("ldmatrix.sync.aligned.m8n8.x4.shared.b16 {%0,%1,%2,%3}, [%4];"
                 : "=r"(r0), "=r"(r1), "=r"(r2), "=r"(r3) : "r"(addr));
}
__device__ __forceinline__ void mma16816(float* c, const unsigned* a,
                                         unsigned b0, unsigned b1) {
    asm volatile("mma.sync.aligned.m16n8k16.row.col.f32.bf16.bf16.f32 "
                 "{%0,%1,%2,%3}, {%4,%5,%6,%7}, {%8,%9}, {%0,%1,%2,%3};"
                 : "+f"(c[0]), "+f"(c[1]), "+f"(c[2]), "+f"(c[3])
                 : "r"(a[0]), "r"(a[1]), "r"(a[2]), "r"(a[3]), "r"(b0), "r"(b1));
}

// ---------------- f32x2 GEMM (R5/R7-proven; gi / e / ctx) --------------------
template <int BM, int BN, int TM, int TN, bool BNC>
__global__ __launch_bounds__((BM / TM) * (BN / TN), 2) void gemm2_k(
    const float* __restrict__ A, const float* __restrict__ A2, int K1,
    const float* __restrict__ Bm, float* __restrict__ Cm, int K,
    int lda, int ldb, int ldc,
    long long a_bs, long long b_bs, long long c_bs,
    const float* __restrict__ bias, int accf, int mode)
{
    constexpr int THREADS = (BM / TM) * (BN / TN);
    constexpr int NTX = BN / TN;
    constexpr int NP  = TM / 2;
    constexpr int NA4 = (BM * BK) / (4 * THREADS);
    constexpr int NB4 = (BN * BK) / (4 * THREADS);
    constexpr int PA  = THREADS / BM;
    constexpr int PB  = THREADS / BN;

    __shared__ __align__(16) float As[2][BK][BM];
    __shared__ __align__(16) float Bs[2][BK][BN];

    const int tid = threadIdx.x;
    const int tx  = tid % NTX;
    const int ty  = tid / NTX;
    const int n0  = blockIdx.x * BN;
    const int m0  = blockIdx.y * BM;
    const float* Ab  = A  + (size_t)blockIdx.z * a_bs;
    const float* A2b = A2 ? (A2 + (size_t)blockIdx.z * a_bs) : nullptr;
    const float* Bb  = Bm + (size_t)blockIdx.z * b_bs;
    float*       Cb  = Cm + (size_t)blockIdx.z * c_bs;

    const int ar  = tid % BM;
    const int akc = tid / BM;
    const float* Ap  = Ab + (size_t)(m0 + ar) * lda + akc * 4;
    const float* Ap2 = A2b ? (A2b + (size_t)(m0 + ar) * lda + akc * 4) : nullptr;

    int bn = 0, bkc = 0, bkr = 0, bn4 = 0;
    const float* Bp;
    if (!BNC) {
        bn  = tid % BN;
        bkc = tid / BN;
        Bp  = Bb + (size_t)(n0 + bn) * ldb + bkc * 4;
    } else {
        bkr = tid >> 5;
        bn4 = (tid & 31) * 4;
        Bp  = Bb + (size_t)bkr * ldb + n0 + bn4;
    }

    u64 acc[NP][TN];
#pragma unroll
    for (int p = 0; p < NP; p++)
#pragma unroll
        for (int j = 0; j < TN; j++) acc[p][j] = 0ull;

    float4 a_r[NA4], b_r[NB4];

    auto LOADA = [&](int kt) {
#pragma unroll
        for (int i = 0; i < NA4; i++) {
            int kcol = kt * BK + 4 * i * PA;
            const float* base = (Ap2 && (kcol + akc * 4) >= K1) ? (Ap2 - K1) : Ap;
            a_r[i] = *(const float4*)(base + kcol);
        }
    };
    auto LOADB = [&](int kt) {
        if (!BNC) {
#pragma unroll
            for (int i = 0; i < NB4; i++)
                b_r[i] = *(const float4*)(Bp + (size_t)kt * BK + 4 * i * PB);
        } else {
#pragma unroll
            for (int i = 0; i < NB4; i++)
                b_r[i] = *(const float4*)(Bp + (size_t)(kt * BK + 4 * i) * ldb);
        }
    };
    auto STORE = [&](int buf) {
#pragma unroll
        for (int i = 0; i < NA4; i++) {
            int k4 = akc + i * PA;
            As[buf][4 * k4 + 0][ar] = a_r[i].x;
            As[buf][4 * k4 + 1][ar] = a_r[i].y;
            As[buf][4 * k4 + 2][ar] = a_r[i].z;
            As[buf][4 * k4 + 3][ar] = a_r[i].w;
        }
        if (!BNC) {
#pragma unroll
            for (int i = 0; i < NB4; i++) {
                int k4 = bkc + i * PB;
                Bs[buf][4 * k4 + 0][bn] = b_r[i].x;
                Bs[buf][4 * k4 + 1][bn] = b_r[i].y;
                Bs[buf][4 * k4 + 2][bn] = b_r[i].z;
                Bs[buf][4 * k4 + 3][bn] = b_r[i].w;
            }
        } else {
#pragma unroll
            for (int i = 0; i < NB4; i++)
                *(float4*)&Bs[buf][bkr + 4 * i][bn4] = b_r[i];
        }
    };

    LOADA(0); LOADB(0);
    STORE(0);
    __syncthreads();

    const int nt = K / BK;
    for (int it = 0; it < nt; it++) {
        const int cur = it & 1;
        if (it + 1 < nt) { LOADA(it + 1); LOADB(it + 1); }

#pragma unroll
        for (int k = 0; k < BK; k++) {
            const float* ask = &As[cur][k][ty * TM];
            const float* bsk = &Bs[cur][k][tx];
            u64 bv[TN];
#pragma unroll
            for (int j = 0; j < TN; j++)
                bv[j] = pack2(bsk[j * NTX]);
            u64 av[NP];
#pragma unroll
            for (int p = 0; p < NP; p++)
                av[p] = *(const u64*)(ask + 2 * p);
#pragma unroll
            for (int p = 0; p < NP; p++)
#pragma unroll
                for (int j = 0; j < TN; j++)
                    ffma2(acc[p][j], av[p], bv[j]);
        }

        if (it + 1 < nt) STORE(cur ^ 1);
        __syncthreads();
    }

    float bj[TN];
#pragma unroll
    for (int j = 0; j < TN; j++)
        bj[j] = bias ? bias[n0 + j * NTX + tx] : 0.f;

#pragma unroll
    for (int p = 0; p < NP; p++) {
        int mA = m0 + ty * TM + 2 * p;
        int mB = mA + 1;
        size_t rA = (mode == 1) ? ((size_t)(mA & 63) * Tq + (mA >> 6)) : (size_t)mA;
        size_t rB = (mode == 1) ? ((size_t)(mB & 63) * Tq + (mB >> 6)) : (size_t)mB;
        float* cpa = Cb + rA * (size_t)ldc + n0;
        float* cpb = Cb + rB * (size_t)ldc + n0;
#pragma unroll
        for (int j = 0; j < TN; j++) {
            float2 f = u2f2(acc[p][j]);
            int off = j * NTX + tx;
            float va = f.x + bj[j];
            float vb = f.y + bj[j];
            if (accf) { va += cpa[off]; vb += cpb[off]; }
            cpa[off] = va;
            cpb[off] = vb;
        }
    }
}

// ============================================================================
// GRU step group (R7-proven): SPT steps/launch, 144 blocks x 256 threads.
// ============================================================================
__device__ __forceinline__ void stepbar(int* cnt, int target)
{
    __syncthreads();
    if (threadIdx.x == 0) {
        __threadfence();
        atomicAdd(cnt, 1);
        while (*(volatile int*)cnt < target) {}
        __threadfence();
    }
    __syncthreads();
}

__global__ __launch_bounds__(256, 1) void gru4_k(
    const float* __restrict__ W_hh, const float* __restrict__ b_hh, int t0)
{
    __shared__ __align__(16) float As[2][BK][64];
    __shared__ __align__(16) float Bs[2][BK][128];

    const int tid = threadIdx.x;
    const int bx  = blockIdx.x;
    const int spl = blockIdx.y;
    const int fbid = spl * 24 + bx;
    const int n0  = bx * 128;
    const int k0  = (spl < 4) ? spl * 176 : 704 + (spl - 4) * 160;
    const int nt  = (spl < 4) ? 11 : 10;

    int* cnt = &d_cnt[t0 / SPT];

    const int ty = tid >> 5;
    const int tx = tid & 31;

    const int ar  = tid & 63;
    const int akc = tid >> 6;
    const int bn  = tid & 127;
    const int bkc = tid >> 7;
    const float* Bp = W_hh + (size_t)(n0 + bn) * Hq + k0 + bkc * 4;

    const int pi = fbid * 256 + tid;
    const int gb = pi >> 9;
    const int gj = (pi & 511) * 2;
    float2 br2, bz2, bn2;
    if (pi < Bq * (Hq / 2)) {
        br2 = *(const float2*)(b_hh + gj);
        bz2 = *(const float2*)(b_hh + Hq + gj);
        bn2 = *(const float2*)(b_hh + 2 * Hq + gj);
    }

    for (int s = 0; s < SPT; s++) {
        const int t = t0 + s;
        const float* Ht = d_H + (size_t)t * Bq * Hq;
        const float* Ap = Ht + (size_t)ar * Hq + k0 + akc * 4;

        u64 acc[4][4];
#pragma unroll
        for (int p = 0; p < 4; p++)
#pragma unroll
            for (int j = 0; j < 4; j++) acc[p][j] = 0ull;

        float4 a_r, b_r[2];
        a_r = *(const float4*)(Ap);
        b_r[0] = *(const float4*)(Bp);
        b_r[1] = *(const float4*)(Bp + 8);

        for (int it = 0; it < nt; it++) {
            const int cur = it & 1;
            As[cur][4 * akc + 0][ar] = a_r.x;
            As[cur][4 * akc + 1][ar] = a_r.y;
            As[cur][4 * akc + 2][ar] = a_r.z;
            As[cur][4 * akc + 3][ar] = a_r.w;
#pragma unroll
            for (int i = 0; i < 2; i++) {
                int k4 = bkc + 2 * i;
                Bs[cur][4 * k4 + 0][bn] = b_r[i].x;
                Bs[cur][4 * k4 + 1][bn] = b_r[i].y;
                Bs[cur][4 * k4 + 2][bn] = b_r[i].z;
                Bs[cur][4 * k4 + 3][bn] = b_r[i].w;
            }
            __syncthreads();
            if (it + 1 < nt) {
                a_r = *(const float4*)(Ap + (it + 1) * BK);
                b_r[0] = *(const float4*)(Bp + (it + 1) * BK);
                b_r[1] = *(const float4*)(Bp + (it + 1) * BK + 8);
            }
#pragma unroll
            for (int k = 0; k < BK; k++) {
                const float* ask = &As[cur][k][ty * 8];
                const float* bsk = &Bs[cur][k][tx];
                u64 bv[4];
#pragma unroll
                for (int j = 0; j < 4; j++) bv[j] = pack2(bsk[j * 32]);
                u64 av[4];
#pragma unroll
                for (int p = 0; p < 4; p++) av[p] = *(const u64*)(ask + 2 * p);
#pragma unroll
                for (int p = 0; p < 4; p++)
#pragma unroll
                    for (int j = 0; j < 4; j++)
                        ffma2(acc[p][j], av[p], bv[j]);
            }
            __syncthreads();
        }

#pragma unroll
        for (int p = 0; p < 4; p++) {
            int bA = ty * 8 + 2 * p;
            float* cpa = &d_ghp[spl][bA][n0];
            float* cpb = &d_ghp[spl][bA + 1][n0];
#pragma unroll
            for (int j = 0; j < 4; j++) {
                float2 f = u2f2(acc[p][j]);
                int off = j * 32 + tx;
                cpa[off] = f.x;
                cpb[off] = f.y;
            }
        }

        stepbar(cnt, NBLK * (2 * s + 1));

        if (pi < Bq * (Hq / 2)) {
            float2 sr = br2, sz = bz2, sn = bn2;
#pragma unroll
            for (int sp = 0; sp < NSPL; sp++) {
                const float* q = &d_ghp[sp][gb][0];
                float2 v;
                v = __ldcg((const float2*)(q + gj));           sr.x += v.x; sr.y += v.y;
                v = __ldcg((const float2*)(q + Hq + gj));      sz.x += v.x; sz.y += v.y;
                v = __ldcg((const float2*)(q + 2 * Hq + gj));  sn.x += v.x; sn.y += v.y;
            }
            const float* gib = d_gi + ((size_t)t * Bq + gb) * G3q;
            float2 gir = *(const float2*)(gib + gj);
            float2 giz = *(const float2*)(gib + Hq + gj);
            float2 gin = *(const float2*)(gib + 2 * Hq + gj);
            float2 hp  = __ldcg((const float2*)(Ht + (size_t)gb * Hq + gj));

            float rx = 1.f / (1.f + expf(-(gir.x + sr.x)));
            float ry = 1.f / (1.f + expf(-(gir.y + sr.y)));
            float zx = 1.f / (1.f + expf(-(giz.x + sz.x)));
            float zy = 1.f / (1.f + expf(-(giz.y + sz.y)));
            float nx = tanhf(gin.x + rx * sn.x);
            float ny = tanhf(gin.y + ry * sn.y);
            float2 hn;
            hn.x = (1.f - zx) * nx + zx * hp.x;
            hn.y = (1.f - zy) * ny + zy * hp.y;
            *(float2*)(d_H + ((size_t)(t + 1) * Bq + gb) * Hq + gj) = hn;
        }

        stepbar(cnt, NBLK * (2 * s + 2));
    }
}

// ============================================================================
// bf16 split conversion kernels
// ============================================================================
__device__ __forceinline__ unsigned bpack(float a, float b, unsigned& lo_out) {
    __nv_bfloat16 ha = __float2bfloat16(a);
    __nv_bfloat16 hb = __float2bfloat16(b);
    __nv_bfloat16 la = __float2bfloat16(a - __bfloat162float(ha));
    __nv_bfloat16 lb = __float2bfloat16(b - __bfloat162float(hb));
    lo_out = ((unsigned)__bfloat16_as_ushort(lb) << 16) | __bfloat16_as_ushort(la);
    return ((unsigned)__bfloat16_as_ushort(hb) << 16) | __bfloat16_as_ushort(ha);
}

__global__ void convA_k()   // A = [h1 | ctx] rows m = t*64+b, 2048 wide
{
    size_t i = (size_t)blockIdx.x * 256 + threadIdx.x;   // float4 index
    int m = (int)(i >> 9);
    int q = (int)(i & 511);
    const float* src = (q < 256)
        ? (d_H + (size_t)(64 + m) * Hq + q * 4)
        : (d_ctx + (size_t)m * Hq + (q - 256) * 4);
    float4 v = *(const float4*)src;
    uint2 hv, lv;
    hv.x = bpack(v.x, v.y, lv.x);
    hv.y = bpack(v.z, v.w, lv.y);
    *(uint2*)(d_Ah + (size_t)m * 2048 + q * 4) = hv;
    *(uint2*)(d_Al + (size_t)m * 2048 + q * 4) = lv;
}

__global__ void convB_k(const float* __restrict__ W_out)
{
    size_t i = (size_t)blockIdx.x * 256 + threadIdx.x;
    float4 v = *(const float4*)(W_out + i * 4);
    uint2 hv, lv;
    hv.x = bpack(v.x, v.y, lv.x);
    hv.y = bpack(v.z, v.w, lv.y);
    *(uint2*)(d_Bh + i * 4) = hv;
    *(uint2*)(d_Bl + i * 4) = lv;
}

// ============================================================================
// Logits GEMM via legacy mma.sync (HMMA): D = A@B^T, 3-term bf16 split,
// fp32 register accumulators. Block 128x128 (8 warps: 2m x 4n, warp 64x32),
// K-chunks of 32, double-buffered smem (row stride 80B: ldmatrix conflict-free).
// Output in (B,T,C) order with bias.
// ============================================================================
#define LROW 80                 // smem row stride in bytes (40 bf16)
#define LT_AH 0
#define LT_AL 10240
#define LT_BH 20480
#define LT_BL 30720
#define LT_BUF 40960

__global__ __launch_bounds__(256, 1)
void logits_hmma_k(const float* __restrict__ b_out, float* __restrict__ out)
{
    extern __shared__ __align__(16) char smem[];
    const unsigned sb = smem_u32(smem);
    const int tid = threadIdx.x;
    const int wid = tid >> 5;
    const int l   = tid & 31;
    const int m0  = blockIdx.x * 128;
    const int n0  = blockIdx.y * 128;
    const int wm  = wid >> 2;        // 0..1
    const int wn  = wid & 3;         // 0..3

    // global staging: each thread 2 uint4 per matrix
    const int grow = tid >> 2;       // 0..63
    const int gseg = tid & 3;        // 8-bf16 segment
    uint4 ra[2], rla[2], rb[2], rlb[2];

    auto GLOAD = [&](int it) {
        int kb = it * 32 + gseg * 8;
#pragma unroll
        for (int h = 0; h < 2; h++) {
            int r = grow + h * 64;
            size_t ga = (size_t)(m0 + r) * 2048 + kb;
            size_t gb = (size_t)(n0 + r) * 2048 + kb;
            ra[h]  = *(const uint4*)(d_Ah + ga);
            rla[h] = *(const uint4*)(d_Al + ga);
            rb[h]  = *(const uint4*)(d_Bh + gb);
            rlb[h] = *(const uint4*)(d_Bl + gb);
        }
    };
    auto SSTORE = [&](int buf) {
        char* base = smem + buf * LT_BUF;
#pragma unroll
        for (int h = 0; h < 2; h++) {
            int off = (grow + h * 64) * LROW + gseg * 16;
            *(uint4*)(base + LT_AH + off) = ra[h];
            *(uint4*)(base + LT_AL + off) = rla[h];
            *(uint4*)(base + LT_BH + off) = rb[h];
            *(uint4*)(base + LT_BL + off) = rlb[h];
        }
    };

    float acc[4][4][4];
#pragma unroll
    for (int mi = 0; mi < 4; mi++)
#pragma unroll
        for (int nj = 0; nj < 4; nj++)
#pragma unroll
            for (int e = 0; e < 4; e++) acc[mi][nj][e] = 0.f;

    // lane-dependent ldmatrix offsets
    const unsigned laneA = (unsigned)((l & 15) * LROW + (l >> 4) * 16);
    const unsigned laneB = (unsigned)(((l & 7) + ((l >> 4) & 1) * 8) * LROW
                                      + ((l >> 3) & 1) * 16);

    GLOAD(0);
    SSTORE(0);
    __syncthreads();

    const int nt = 2048 / 32;   // 64
    for (int it = 0; it < nt; it++) {
        const int cur = it & 1;
        if (it + 1 < nt) GLOAD(it + 1);

        const unsigned abase = sb + cur * LT_BUF + (unsigned)(wm * 64) * LROW;
        const unsigned bbase = sb + cur * LT_BUF + (unsigned)(wn * 32) * LROW;

#pragma unroll
        for (int kk = 0; kk < 2; kk++) {
            const unsigned kb = kk * 32;   // 16 bf16 = 32 bytes
            unsigned ah[4][4], al[4][4];
#pragma unroll
            for (int mi = 0; mi < 4; mi++) {
                unsigned ao = abase + (unsigned)(mi * 16) * LROW + kb + laneA;
                ldsm4(ah[mi][0], ah[mi][1], ah[mi][2], ah[mi][3], ao + LT_AH);
                ldsm4(al[mi][0], al[mi][1], al[mi][2], al[mi][3], ao + LT_AL);
            }
            unsigned bh[2][4], bl[2][4];
#pragma unroll
            for (int nh = 0; nh < 2; nh++) {
                unsigned bo = bbase + (unsigned)(nh * 16) * LROW + kb + laneB;
                ldsm4(bh[nh][0], bh[nh][1], bh[nh][2], bh[nh][3], bo + LT_BH);
                ldsm4(bl[nh][0], bl[nh][1], bl[nh][2], bl[nh][3], bo + LT_BL);
            }
#pragma unroll
            for (int mi = 0; mi < 4; mi++)
#pragma unroll
                for (int nj = 0; nj < 4; nj++) {
                    const int nh = nj >> 1, ns = (nj & 1) * 2;
                    mma16816(acc[mi][nj], ah[mi], bh[nh][ns], bh[nh][ns + 1]);
                    mma16816(acc[mi][nj], al[mi], bh[nh][ns], bh[nh][ns + 1]);
                    mma16816(acc[mi][nj], ah[mi], bl[nh][ns], bl[nh][ns + 1]);
                }
        }

        if (it + 1 < nt) SSTORE(cur ^ 1);
        __syncthreads();
    }

    // epilogue: c frag lane mapping — rows l/4 and l/4+8, cols (l%4)*2, +1
#pragma unroll
    for (int nj = 0; nj < 4; nj++) {
        const int n = n0 + wn * 32 + nj * 8 + (l & 3) * 2;
        const float2 bo = *(const float2*)(b_out + n);
#pragma unroll
        for (int mi = 0; mi < 4; mi++) {
            int mA = m0 + wm * 64 + mi * 16 + (l >> 2);
            int mB = mA + 8;
            float* pa = out + ((size_t)(mA & 63) * Tq + (mA >> 6)) * Cq + n;
            float* pb = out + ((size_t)(mB & 63) * Tq + (mB >> 6)) * Cq + n;
            float2 va = make_float2(acc[mi][nj][0] + bo.x, acc[mi][nj][1] + bo.y);
            float2 vb = make_float2(acc[mi][nj][2] + bo.x, acc[mi][nj][3] + bo.y);
            *(float2*)pa = va;
            *(float2*)pb = vb;
        }
    }
}

// ---------------- small kernels ----------------------------------------------
__global__ void embed_k(const int* __restrict__ targets, const float* __restrict__ E)
{
    int m = blockIdx.x;
    int t = m >> 6, b = m & 63;
    int id = (t == 0) ? 0 : targets[b * Tq + (t - 1)];
    const float4* src = (const float4*)(E + (size_t)id * WEq);
    float4* dst = (float4*)(d_X + (size_t)m * WEq);
    dst[threadIdx.x] = src[threadIdx.x];
}

__global__ void words_k(const unsigned char* __restrict__ mask8)
{
    int b = blockIdx.x, t = threadIdx.x;
    int is8 = (mask8[1] != 0);
    int v;
    if (is8) v = mask8[b * Tq + t] ? 1 : 0;
    else     v = ((const int*)mask8)[b * Tq + t] ? 1 : 0;
#pragma unroll
    for (int o = 16; o; o >>= 1) v += __shfl_down_sync(0xffffffffu, v, o);
    __shared__ int red[8];
    if ((t & 31) == 0) red[t >> 5] = v;
    __syncthreads();
    if (t == 0) {
        int s = 0;
#pragma unroll
        for (int i = 0; i < 8; i++) s += red[i];
        d_words[b] = s;
    }
}

__global__ void h0_k(const float* __restrict__ enc)
{
    int b = blockIdx.x;
    const float4* src = (const float4*)(enc + ((size_t)b * Tq + (Tq - 1)) * Hq);
    float4* dst = (float4*)(d_H + (size_t)b * Hq);
    dst[threadIdx.x] = src[threadIdx.x];
}

__global__ void softmax_k()
{
    int m = blockIdx.x;
    int b = m & (Bq - 1);
    int wn = d_words[b];
    float* e = d_e + (size_t)m * Tq;
    int s = threadIdx.x;
    float v = (s < wn) ? e[s] : -3.0e38f;

    __shared__ float red[8];
    __shared__ float smax, ssum;
    float mx = v;
#pragma unroll
    for (int o = 16; o; o >>= 1) mx = fmaxf(mx, __shfl_xor_sync(0xffffffffu, mx, o));
    if ((s & 31) == 0) red[s >> 5] = mx;
    __syncthreads();
    if (s == 0) {
        float x = red[0];
#pragma unroll
        for (int i = 1; i < 8; i++) x = fmaxf(x, red[i]);
        smax = x;
    }
    __syncthreads();
    float ex = (s < wn) ? expf(v - smax) : 0.f;
    float sum = ex;
#pragma unroll
    for (int o = 16; o; o >>= 1) sum += __shfl_xor_sync(0xffffffffu, sum, o);
    if ((s & 31) == 0) red[s >> 5] = sum;
    __syncthreads();
    if (s == 0) {
        float x = 0.f;
#pragma unroll
        for (int i = 0; i < 8; i++) x += red[i];
        ssum = 1.f / x;
    }
    __syncthreads();
    e[s] = ex * ssum;
}

// ---------------- launch ------------------------------------------------------
extern "C" void kernel_launch(void* const* d_in, const int* in_sizes, int n_in,
                              void* d_out, int out_size)
{
    const float*         enc     = (const float*)d_in[0];
    const unsigned char* mask    = (const unsigned char*)d_in[1];
    const int*           targets = (const int*)d_in[2];
    const float*         E       = (const float*)d_in[3];
    const float*         W_ih    = (const float*)d_in[4];
    const float*         W_hh    = (const float*)d_in[5];
    const float*         b_ih    = (const float*)d_in[6];
    const float*         b_hh    = (const float*)d_in[7];
    const float*         W_out   = (const float*)d_in[8];
    const float*         b_out   = (const float*)d_in[9];
    float* out = (float*)d_out;

    void* p;
    cudaGetSymbolAddress(&p, d_X);   float* X   = (float*)p;
    cudaGetSymbolAddress(&p, d_gi);  float* GI  = (float*)p;
    cudaGetSymbolAddress(&p, d_H);   float* Hh  = (float*)p;
    cudaGetSymbolAddress(&p, d_e);   float* Ee  = (float*)p;
    cudaGetSymbolAddress(&p, d_ctx); float* CTX = (float*)p;
    void* cntp;
    cudaGetSymbolAddress(&cntp, d_cnt);

    cudaFuncSetAttribute(logits_hmma_k,
                         cudaFuncAttributeMaxDynamicSharedMemorySize,
                         2 * LT_BUF);

    // Phase 0
    cudaMemsetAsync(cntp, 0, (Tq / SPT) * sizeof(int));
    embed_k<<<Tq * Bq, 64>>>(targets, E);
    words_k<<<Bq, 256>>>(mask);
    h0_k<<<Bq, 256>>>(enc);
    // W_out bf16 split (independent of recurrence; do it early)
    convB_k<<<(Cq * 2048 / 4) / 256, 256>>>(W_out);

    // Phase 1: gi = X @ W_ih^T + b_ih
    gemm2_k<128, 128, 16, 8, false><<<dim3(G3q / 128, (Tq * Bq) / 128, 1), 128>>>(
        X, nullptr, 1 << 30, W_ih, GI, WEq, WEq, WEq, G3q, 0, 0, 0, b_ih, 0, 0);

    // Phase 2: GRU recurrence (R7-proven)
    for (int t0 = 0; t0 < Tq; t0 += SPT)
        gru4_k<<<dim3(24, NSPL), 256>>>(W_hh, b_hh, t0);

    // Phase 3a: e[t,b,s]
    gemm2_k<128, 128, 16, 8, false><<<dim3(Tq / 128, Tq / 128, Bq), 128>>>(
        Hh + (size_t)Bq * Hq, nullptr, 1 << 30, enc, Ee, Hq,
        Bq * Hq, Hq, Bq * Tq,
        Hq, (long long)Tq * Hq, Tq,
        nullptr, 0, 0);

    // Phase 3b: masked softmax
    softmax_k<<<Tq * Bq, Tq>>>();

    // Phase 3c: ctx
    gemm2_k<128, 128, 16, 8, true><<<dim3(Hq / 128, Tq / 128, Bq), 128>>>(
        Ee, nullptr, 1 << 30, enc, CTX, Tq,
        Bq * Tq, Hq, Bq * Hq,
        Tq, (long long)Tq * Hq, Hq,
        nullptr, 0, 0);

    // Phase 4: logits on legacy HMMA (3-term bf16 split, fp32 accum)
    convA_k<<<(Tq * Bq * 2048 / 4) / 256, 256>>>();
    logits_hmma_k<<<dim3((Tq * Bq) / 128, Cq / 128), 256, 2 * LT_BUF>>>(b_out, out);
}

// round 14
// speedup vs baseline: 1.2488x; 1.2488x over previous
#include <cuda_runtime.h>
#include <math.h>
#include <stdint.h>

// Problem constants
#define Bq   64
#define Tq   256
#define Cq   2048
#define WEq  256
#define Hq   1024
#define G3q  3072
#define BK   16
#define NSPL 6
#define NBLK 144
#define SPT  8          // GRU steps per launch (32 launches)

typedef unsigned long long u64;

// ---------------- scratch (device globals) -----------------------------------
__device__ float d_X  [Tq * Bq * WEq];
__device__ float d_gi [(size_t)Tq * Bq * G3q];   // [t][b][n]
__device__ float d_H  [(Tq + 1) * Bq * Hq];      // [t][b][j]
__device__ float d_ghp[NSPL][Bq][G3q];           // [split][b][n]
__device__ float d_e  [Tq * Bq * Tq];
__device__ float d_ctx[(size_t)Tq * Bq * Hq];
__device__ int   d_words[Bq];
__device__ int   d_cnt[Tq / SPT][8 * 32];        // 8 padded sub-counters / group

// ---------------- f32x2 helpers ----------------------------------------------
__device__ __forceinline__ void ffma2(u64& d, u64 a, u64 b) {
    asm("fma.rn.f32x2 %0, %1, %2, %0;" : "+l"(d) : "l"(a), "l"(b));
}
__device__ __forceinline__ float2 u2f2(u64 v) {
    unsigned lo, hi;
    asm("mov.b64 {%0, %1}, %2;" : "=r"(lo), "=r"(hi) : "l"(v));
    return make_float2(__uint_as_float(lo), __uint_as_float(hi));
}
__device__ __forceinline__ u64 pack2(float x) {
    u64 r;
    asm("mov.b64 %0, {%1, %1};" : "=l"(r) : "f"(x));
    return r;
}

// ---------------- f32x2 GEMM (R5/R7-proven; gi / e / ctx / logits) -----------
template <int BM, int BN, int TM, int TN, bool BNC>
__global__ __launch_bounds__((BM / TM) * (BN / TN), 2) void gemm2_k(
    const float* __restrict__ A, const float* __restrict__ A2, int K1,
    const float* __restrict__ Bm, float* __restrict__ Cm, int K,
    int lda, int ldb, int ldc,
    long long a_bs, long long b_bs, long long c_bs,
    const float* __restrict__ bias, int accf, int mode)
{
    constexpr int THREADS = (BM / TM) * (BN / TN);
    constexpr int NTX = BN / TN;
    constexpr int NP  = TM / 2;
    constexpr int NA4 = (BM * BK) / (4 * THREADS);
    constexpr int NB4 = (BN * BK) / (4 * THREADS);
    constexpr int PA  = THREADS / BM;
    constexpr int PB  = THREADS / BN;

    __shared__ __align__(16) float As[2][BK][BM];
    __shared__ __align__(16) float Bs[2][BK][BN];

    const int tid = threadIdx.x;
    const int tx  = tid % NTX;
    const int ty  = tid / NTX;
    const int n0  = blockIdx.x * BN;
    const int m0  = blockIdx.y * BM;
    const float* Ab  = A  + (size_t)blockIdx.z * a_bs;
    const float* A2b = A2 ? (A2 + (size_t)blockIdx.z * a_bs) : nullptr;
    const float* Bb  = Bm + (size_t)blockIdx.z * b_bs;
    float*       Cb  = Cm + (size_t)blockIdx.z * c_bs;

    const int ar  = tid % BM;
    const int akc = tid / BM;
    const float* Ap  = Ab + (size_t)(m0 + ar) * lda + akc * 4;
    const float* Ap2 = A2b ? (A2b + (size_t)(m0 + ar) * lda + akc * 4) : nullptr;

    int bn = 0, bkc = 0, bkr = 0, bn4 = 0;
    const float* Bp;
    if (!BNC) {
        bn  = tid % BN;
        bkc = tid / BN;
        Bp  = Bb + (size_t)(n0 + bn) * ldb + bkc * 4;
    } else {
        bkr = tid >> 5;
        bn4 = (tid & 31) * 4;
        Bp  = Bb + (size_t)bkr * ldb + n0 + bn4;
    }

    u64 acc[NP][TN];
#pragma unroll
    for (int p = 0; p < NP; p++)
#pragma unroll
        for (int j = 0; j < TN; j++) acc[p][j] = 0ull;

    float4 a_r[NA4], b_r[NB4];

    auto LOADA = [&](int kt) {
#pragma unroll
        for (int i = 0; i < NA4; i++) {
            int kcol = kt * BK + 4 * i * PA;
            const float* base = (Ap2 && (kcol + akc * 4) >= K1) ? (Ap2 - K1) : Ap;
            a_r[i] = *(const float4*)(base + kcol);
        }
    };
    auto LOADB = [&](int kt) {
        if (!BNC) {
#pragma unroll
            for (int i = 0; i < NB4; i++)
                b_r[i] = *(const float4*)(Bp + (size_t)kt * BK + 4 * i * PB);
        } else {
#pragma unroll
            for (int i = 0; i < NB4; i++)
                b_r[i] = *(const float4*)(Bp + (size_t)(kt * BK + 4 * i) * ldb);
        }
    };
    auto STORE = [&](int buf) {
#pragma unroll
        for (int i = 0; i < NA4; i++) {
            int k4 = akc + i * PA;
            As[buf][4 * k4 + 0][ar] = a_r[i].x;
            As[buf][4 * k4 + 1][ar] = a_r[i].y;
            As[buf][4 * k4 + 2][ar] = a_r[i].z;
            As[buf][4 * k4 + 3][ar] = a_r[i].w;
        }
        if (!BNC) {
#pragma unroll
            for (int i = 0; i < NB4; i++) {
                int k4 = bkc + i * PB;
                Bs[buf][4 * k4 + 0][bn] = b_r[i].x;
                Bs[buf][4 * k4 + 1][bn] = b_r[i].y;
                Bs[buf][4 * k4 + 2][bn] = b_r[i].z;
                Bs[buf][4 * k4 + 3][bn] = b_r[i].w;
            }
        } else {
#pragma unroll
            for (int i = 0; i < NB4; i++)
                *(float4*)&Bs[buf][bkr + 4 * i][bn4] = b_r[i];
        }
    };

    LOADA(0); LOADB(0);
    STORE(0);
    __syncthreads();

    const int nt = K / BK;
    for (int it = 0; it < nt; it++) {
        const int cur = it & 1;
        if (it + 1 < nt) { LOADA(it + 1); LOADB(it + 1); }

#pragma unroll
        for (int k = 0; k < BK; k++) {
            const float* ask = &As[cur][k][ty * TM];
            const float* bsk = &Bs[cur][k][tx];
            u64 bv[TN];
#pragma unroll
            for (int j = 0; j < TN; j++)
                bv[j] = pack2(bsk[j * NTX]);
            u64 av[NP];
#pragma unroll
            for (int p = 0; p < NP; p++)
                av[p] = *(const u64*)(ask + 2 * p);
#pragma unroll
            for (int p = 0; p < NP; p++)
#pragma unroll
                for (int j = 0; j < TN; j++)
                    ffma2(acc[p][j], av[p], bv[j]);
        }

        if (it + 1 < nt) STORE(cur ^ 1);
        __syncthreads();
    }

    float bj[TN];
#pragma unroll
    for (int j = 0; j < TN; j++)
        bj[j] = bias ? bias[n0 + j * NTX + tx] : 0.f;

#pragma unroll
    for (int p = 0; p < NP; p++) {
        int mA = m0 + ty * TM + 2 * p;
        int mB = mA + 1;
        size_t rA = (mode == 1) ? ((size_t)(mA & 63) * Tq + (mA >> 6)) : (size_t)mA;
        size_t rB = (mode == 1) ? ((size_t)(mB & 63) * Tq + (mB >> 6)) : (size_t)mB;
        float* cpa = Cb + rA * (size_t)ldc + n0;
        float* cpb = Cb + rB * (size_t)ldc + n0;
#pragma unroll
        for (int j = 0; j < TN; j++) {
            float2 f = u2f2(acc[p][j]);
            int off = j * NTX + tx;
            float va = f.x + bj[j];
            float vb = f.y + bj[j];
            if (accf) { va += cpa[off]; vb += cpb[off]; }
            cpa[off] = va;
            cpb[off] = vb;
        }
    }
}

// ============================================================================
// GRU step group: SPT steps/launch, 144 blocks x 256 threads.
// Grid barrier via 8 PADDED SUB-COUNTERS: arrivals spread over 8 cache lines
// (18 serialized atomics each instead of 144 on one line), spinners sum 8.
// ============================================================================
__device__ __forceinline__ void stepbar(int* cnt, int sub, int target)
{
    __syncthreads();
    if (threadIdx.x == 0) {
        __threadfence();
        atomicAdd(cnt + sub * 32, 1);
        int s;
        do {
            s = 0;
#pragma unroll
            for (int i = 0; i < 8; i++)
                s += *(volatile int*)(cnt + i * 32);
        } while (s < target);
        __threadfence();
    }
    __syncthreads();
}

__global__ __launch_bounds__(256, 1) void gru4_k(
    const float* __restrict__ W_hh, const float* __restrict__ b_hh, int t0)
{
    __shared__ __align__(16) float As[2][BK][64];
    __shared__ __align__(16) float Bs[2][BK][128];

    const int tid = threadIdx.x;
    const int bx  = blockIdx.x;
    const int spl = blockIdx.y;
    const int fbid = spl * 24 + bx;
    const int n0  = bx * 128;
    const int k0  = (spl < 4) ? spl * 176 : 704 + (spl - 4) * 160;
    const int nt  = (spl < 4) ? 11 : 10;

    int* cnt = &d_cnt[t0 / SPT][0];
    const int sub = fbid & 7;

    const int ty = tid >> 5;
    const int tx = tid & 31;

    const int ar  = tid & 63;
    const int akc = tid >> 6;
    const int bn  = tid & 127;
    const int bkc = tid >> 7;
    const float* Bp = W_hh + (size_t)(n0 + bn) * Hq + k0 + bkc * 4;

    const int pi = fbid * 256 + tid;
    const int gb = pi >> 9;
    const int gj = (pi & 511) * 2;
    float2 br2, bz2, bn2;
    if (pi < Bq * (Hq / 2)) {
        br2 = *(const float2*)(b_hh + gj);
        bz2 = *(const float2*)(b_hh + Hq + gj);
        bn2 = *(const float2*)(b_hh + 2 * Hq + gj);
    }

    for (int s = 0; s < SPT; s++) {
        const int t = t0 + s;
        const float* Ht = d_H + (size_t)t * Bq * Hq;
        const float* Ap = Ht + (size_t)ar * Hq + k0 + akc * 4;

        u64 acc[4][4];
#pragma unroll
        for (int p = 0; p < 4; p++)
#pragma unroll
            for (int j = 0; j < 4; j++) acc[p][j] = 0ull;

        float4 a_r, b_r[2];
        a_r = *(const float4*)(Ap);
        b_r[0] = *(const float4*)(Bp);
        b_r[1] = *(const float4*)(Bp + 8);

        for (int it = 0; it < nt; it++) {
            const int cur = it & 1;
            As[cur][4 * akc + 0][ar] = a_r.x;
            As[cur][4 * akc + 1][ar] = a_r.y;
            As[cur][4 * akc + 2][ar] = a_r.z;
            As[cur][4 * akc + 3][ar] = a_r.w;
#pragma unroll
            for (int i = 0; i < 2; i++) {
                int k4 = bkc + 2 * i;
                Bs[cur][4 * k4 + 0][bn] = b_r[i].x;
                Bs[cur][4 * k4 + 1][bn] = b_r[i].y;
                Bs[cur][4 * k4 + 2][bn] = b_r[i].z;
                Bs[cur][4 * k4 + 3][bn] = b_r[i].w;
            }
            __syncthreads();
            if (it + 1 < nt) {
                a_r = *(const float4*)(Ap + (it + 1) * BK);
                b_r[0] = *(const float4*)(Bp + (it + 1) * BK);
                b_r[1] = *(const float4*)(Bp + (it + 1) * BK + 8);
            }
#pragma unroll
            for (int k = 0; k < BK; k++) {
                const float* ask = &As[cur][k][ty * 8];
                const float* bsk = &Bs[cur][k][tx];
                u64 bv[4];
#pragma unroll
                for (int j = 0; j < 4; j++) bv[j] = pack2(bsk[j * 32]);
                u64 av[4];
#pragma unroll
                for (int p = 0; p < 4; p++) av[p] = *(const u64*)(ask + 2 * p);
#pragma unroll
                for (int p = 0; p < 4; p++)
#pragma unroll
                    for (int j = 0; j < 4; j++)
                        ffma2(acc[p][j], av[p], bv[j]);
            }
            __syncthreads();
        }

#pragma unroll
        for (int p = 0; p < 4; p++) {
            int bA = ty * 8 + 2 * p;
            float* cpa = &d_ghp[spl][bA][n0];
            float* cpb = &d_ghp[spl][bA + 1][n0];
#pragma unroll
            for (int j = 0; j < 4; j++) {
                float2 f = u2f2(acc[p][j]);
                int off = j * 32 + tx;
                cpa[off] = f.x;
                cpb[off] = f.y;
            }
        }

        stepbar(cnt, sub, NBLK * (2 * s + 1));

        if (pi < Bq * (Hq / 2)) {
            float2 sr = br2, sz = bz2, sn = bn2;
#pragma unroll
            for (int sp = 0; sp < NSPL; sp++) {
                const float* q = &d_ghp[sp][gb][0];
                float2 v;
                v = __ldcg((const float2*)(q + gj));           sr.x += v.x; sr.y += v.y;
                v = __ldcg((const float2*)(q + Hq + gj));      sz.x += v.x; sz.y += v.y;
                v = __ldcg((const float2*)(q + 2 * Hq + gj));  sn.x += v.x; sn.y += v.y;
            }
            const float* gib = d_gi + ((size_t)t * Bq + gb) * G3q;
            float2 gir = *(const float2*)(gib + gj);
            float2 giz = *(const float2*)(gib + Hq + gj);
            float2 gin = *(const float2*)(gib + 2 * Hq + gj);
            float2 hp  = __ldcg((const float2*)(Ht + (size_t)gb * Hq + gj));

            float rx = 1.f / (1.f + expf(-(gir.x + sr.x)));
            float ry = 1.f / (1.f + expf(-(gir.y + sr.y)));
            float zx = 1.f / (1.f + expf(-(giz.x + sz.x)));
            float zy = 1.f / (1.f + expf(-(giz.y + sz.y)));
            float nx = tanhf(gin.x + rx * sn.x);
            float ny = tanhf(gin.y + ry * sn.y);
            float2 hn;
            hn.x = (1.f - zx) * nx + zx * hp.x;
            hn.y = (1.f - zy) * ny + zy * hp.y;
            *(float2*)(d_H + ((size_t)(t + 1) * Bq + gb) * Hq + gj) = hn;
        }

        stepbar(cnt, sub, NBLK * (2 * s + 2));
    }
}

// ---------------- small kernels ----------------------------------------------
__global__ void embed_k(const int* __restrict__ targets, const float* __restrict__ E)
{
    int m = blockIdx.x;
    int t = m >> 6, b = m & 63;
    int id = (t == 0) ? 0 : targets[b * Tq + (t - 1)];
    const float4* src = (const float4*)(E + (size_t)id * WEq);
    float4* dst = (float4*)(d_X + (size_t)m * WEq);
    dst[threadIdx.x] = src[threadIdx.x];
}

__global__ void words_k(const unsigned char* __restrict__ mask8)
{
    int b = blockIdx.x, t = threadIdx.x;
    int is8 = (mask8[1] != 0);
    int v;
    if (is8) v = mask8[b * Tq + t] ? 1 : 0;
    else     v = ((const int*)mask8)[b * Tq + t] ? 1 : 0;
#pragma unroll
    for (int o = 16; o; o >>= 1) v += __shfl_down_sync(0xffffffffu, v, o);
    __shared__ int red[8];
    if ((t & 31) == 0) red[t >> 5] = v;
    __syncthreads();
    if (t == 0) {
        int s = 0;
#pragma unroll
        for (int i = 0; i < 8; i++) s += red[i];
        d_words[b] = s;
    }
}

__global__ void h0_k(const float* __restrict__ enc)
{
    int b = blockIdx.x;
    const float4* src = (const float4*)(enc + ((size_t)b * Tq + (Tq - 1)) * Hq);
    float4* dst = (float4*)(d_H + (size_t)b * Hq);
    dst[threadIdx.x] = src[threadIdx.x];
}

__global__ void softmax_k()
{
    int m = blockIdx.x;
    int b = m & (Bq - 1);
    int wn = d_words[b];
    float* e = d_e + (size_t)m * Tq;
    int s = threadIdx.x;
    float v = (s < wn) ? e[s] : -3.0e38f;

    __shared__ float red[8];
    __shared__ float smax, ssum;
    float mx = v;
#pragma unroll
    for (int o = 16; o; o >>= 1) mx = fmaxf(mx, __shfl_xor_sync(0xffffffffu, mx, o));
    if ((s & 31) == 0) red[s >> 5] = mx;
    __syncthreads();
    if (s == 0) {
        float x = red[0];
#pragma unroll
        for (int i = 1; i < 8; i++) x = fmaxf(x, red[i]);
        smax = x;
    }
    __syncthreads();
    float ex = (s < wn) ? expf(v - smax) : 0.f;
    float sum = ex;
#pragma unroll
    for (int o = 16; o; o >>= 1) sum += __shfl_xor_sync(0xffffffffu, sum, o);
    if ((s & 31) == 0) red[s >> 5] = sum;
    __syncthreads();
    if (s == 0) {
        float x = 0.f;
#pragma unroll
        for (int i = 0; i < 8; i++) x += red[i];
        ssum = 1.f / x;
    }
    __syncthreads();
    e[s] = ex * ssum;
}

// ---------------- launch ------------------------------------------------------
extern "C" void kernel_launch(void* const* d_in, const int* in_sizes, int n_in,
                              void* d_out, int out_size)
{
    const float*         enc     = (const float*)d_in[0];
    const unsigned char* mask    = (const unsigned char*)d_in[1];
    const int*           targets = (const int*)d_in[2];
    const float*         E       = (const float*)d_in[3];
    const float*         W_ih    = (const float*)d_in[4];
    const float*         W_hh    = (const float*)d_in[5];
    const float*         b_ih    = (const float*)d_in[6];
    const float*         b_hh    = (const float*)d_in[7];
    const float*         W_out   = (const float*)d_in[8];
    const float*         b_out   = (const float*)d_in[9];
    float* out = (float*)d_out;

    void* p;
    cudaGetSymbolAddress(&p, d_X);   float* X   = (float*)p;
    cudaGetSymbolAddress(&p, d_gi);  float* GI  = (float*)p;
    cudaGetSymbolAddress(&p, d_H);   float* Hh  = (float*)p;
    cudaGetSymbolAddress(&p, d_e);   float* Ee  = (float*)p;
    cudaGetSymbolAddress(&p, d_ctx); float* CTX = (float*)p;
    void* cntp;
    cudaGetSymbolAddress(&cntp, d_cnt);

    // Phase 0
    cudaMemsetAsync(cntp, 0, (Tq / SPT) * 8 * 32 * sizeof(int));
    embed_k<<<Tq * Bq, 64>>>(targets, E);
    words_k<<<Bq, 256>>>(mask);
    h0_k<<<Bq, 256>>>(enc);

    // Phase 1: gi = X @ W_ih^T + b_ih   (16384 x 3072 x 256), layout [t][b][n]
    gemm2_k<128, 128, 16, 8, false><<<dim3(G3q / 128, (Tq * Bq) / 128, 1), 128>>>(
        X, nullptr, 1 << 30, W_ih, GI, WEq, WEq, WEq, G3q, 0, 0, 0, b_ih, 0, 0);

    // Phase 2: GRU recurrence — SPT steps/launch, sub-counter grid barrier
    for (int t0 = 0; t0 < Tq; t0 += SPT)
        gru4_k<<<dim3(24, NSPL), 256>>>(W_hh, b_hh, t0);

    // Phase 3a: e[t,b,s] = h1[t,b,:] . enc[b,s,:]
    gemm2_k<128, 128, 16, 8, false><<<dim3(Tq / 128, Tq / 128, Bq), 128>>>(
        Hh + (size_t)Bq * Hq, nullptr, 1 << 30, enc, Ee, Hq,
        Bq * Hq, Hq, Bq * Tq,
        Hq, (long long)Tq * Hq, Tq,
        nullptr, 0, 0);

    // Phase 3b: masked softmax
    softmax_k<<<Tq * Bq, Tq>>>();

    // Phase 3c: ctx[t,b,:] = alpha[t,b,:] @ enc[b]   (B n-contiguous)
    gemm2_k<128, 128, 16, 8, true><<<dim3(Hq / 128, Tq / 128, Bq), 128>>>(
        Ee, nullptr, 1 << 30, enc, CTX, Tq,
        Bq * Tq, Hq, Bq * Hq,
        Tq, (long long)Tq * Hq, Hq,
        nullptr, 0, 0);

    // Phase 4: logits = [h1 | ctx] @ W_out^T + b_out, concat K=2048, (B,T,C) out
    gemm2_k<128, 128, 16, 8, false><<<dim3(Cq / 128, (Tq * Bq) / 128, 1), 128>>>(
        Hh + (size_t)Bq * Hq, CTX, Hq, W_out, out, 2 * Hq,
        Hq, 2 * Hq, Cq, 0, 0, 0, b_out, 0, 1);
}

// round 16
// speedup vs baseline: 1.2786x; 1.0239x over previous
#include <cuda_runtime.h>
#include <math.h>
#include <stdint.h>

// Problem constants
#define Bq   64
#define Tq   256
#define Cq   2048
#define WEq  256
#define Hq   1024
#define G3q  3072
#define BK   16
#define NSPL 12          // k-splits for step GEMM (88x8, 80x4)
#define NBGRU 288        // 24 n-tiles x 12 splits (<= 2*148, all co-resident)
#define SPT  8           // GRU steps per launch (32 launches)

typedef unsigned long long u64;

// ---------------- scratch (device globals) -----------------------------------
__device__ float d_X  [Tq * Bq * WEq];
__device__ float d_gi [(size_t)Tq * Bq * G3q];   // [t][b][n]
__device__ float d_H  [(Tq + 1) * Bq * Hq];      // [t][b][j]
__device__ float d_ghp[NSPL][Bq][G3q];           // [split][b][n]
__device__ float d_e  [Tq * Bq * Tq];
__device__ float d_ctx[(size_t)Tq * Bq * Hq];
__device__ int   d_words[Bq];
__device__ int   d_cnt[Tq / SPT][8 * 32];        // 8 padded sub-counters / group

// ---------------- f32x2 helpers ----------------------------------------------
__device__ __forceinline__ void ffma2(u64& d, u64 a, u64 b) {
    asm("fma.rn.f32x2 %0, %1, %2, %0;" : "+l"(d) : "l"(a), "l"(b));
}
__device__ __forceinline__ float2 u2f2(u64 v) {
    unsigned lo, hi;
    asm("mov.b64 {%0, %1}, %2;" : "=r"(lo), "=r"(hi) : "l"(v));
    return make_float2(__uint_as_float(lo), __uint_as_float(hi));
}
__device__ __forceinline__ u64 pack2(float x) {
    u64 r;
    asm("mov.b64 %0, {%1, %1};" : "=l"(r) : "f"(x));
    return r;
}

// ---------------- f32x2 GEMM (R5/R7-proven; gi / e / ctx / logits) -----------
template <int BM, int BN, int TM, int TN, bool BNC>
__global__ __launch_bounds__((BM / TM) * (BN / TN), 2) void gemm2_k(
    const float* __restrict__ A, const float* __restrict__ A2, int K1,
    const float* __restrict__ Bm, float* __restrict__ Cm, int K,
    int lda, int ldb, int ldc,
    long long a_bs, long long b_bs, long long c_bs,
    const float* __restrict__ bias, int accf, int mode)
{
    constexpr int THREADS = (BM / TM) * (BN / TN);
    constexpr int NTX = BN / TN;
    constexpr int NP  = TM / 2;
    constexpr int NA4 = (BM * BK) / (4 * THREADS);
    constexpr int NB4 = (BN * BK) / (4 * THREADS);
    constexpr int PA  = THREADS / BM;
    constexpr int PB  = THREADS / BN;

    __shared__ __align__(16) float As[2][BK][BM];
    __shared__ __align__(16) float Bs[2][BK][BN];

    const int tid = threadIdx.x;
    const int tx  = tid % NTX;
    const int ty  = tid / NTX;
    const int n0  = blockIdx.x * BN;
    const int m0  = blockIdx.y * BM;
    const float* Ab  = A  + (size_t)blockIdx.z * a_bs;
    const float* A2b = A2 ? (A2 + (size_t)blockIdx.z * a_bs) : nullptr;
    const float* Bb  = Bm + (size_t)blockIdx.z * b_bs;
    float*       Cb  = Cm + (size_t)blockIdx.z * c_bs;

    const int ar  = tid % BM;
    const int akc = tid / BM;
    const float* Ap  = Ab + (size_t)(m0 + ar) * lda + akc * 4;
    const float* Ap2 = A2b ? (A2b + (size_t)(m0 + ar) * lda + akc * 4) : nullptr;

    int bn = 0, bkc = 0, bkr = 0, bn4 = 0;
    const float* Bp;
    if (!BNC) {
        bn  = tid % BN;
        bkc = tid / BN;
        Bp  = Bb + (size_t)(n0 + bn) * ldb + bkc * 4;
    } else {
        bkr = tid >> 5;
        bn4 = (tid & 31) * 4;
        Bp  = Bb + (size_t)bkr * ldb + n0 + bn4;
    }

    u64 acc[NP][TN];
#pragma unroll
    for (int p = 0; p < NP; p++)
#pragma unroll
        for (int j = 0; j < TN; j++) acc[p][j] = 0ull;

    float4 a_r[NA4], b_r[NB4];

    auto LOADA = [&](int kt) {
#pragma unroll
        for (int i = 0; i < NA4; i++) {
            int kcol = kt * BK + 4 * i * PA;
            const float* base = (Ap2 && (kcol + akc * 4) >= K1) ? (Ap2 - K1) : Ap;
            a_r[i] = *(const float4*)(base + kcol);
        }
    };
    auto LOADB = [&](int kt) {
        if (!BNC) {
#pragma unroll
            for (int i = 0; i < NB4; i++)
                b_r[i] = *(const float4*)(Bp + (size_t)kt * BK + 4 * i * PB);
        } else {
#pragma unroll
            for (int i = 0; i < NB4; i++)
                b_r[i] = *(const float4*)(Bp + (size_t)(kt * BK + 4 * i) * ldb);
        }
    };
    auto STORE = [&](int buf) {
#pragma unroll
        for (int i = 0; i < NA4; i++) {
            int k4 = akc + i * PA;
            As[buf][4 * k4 + 0][ar] = a_r[i].x;
            As[buf][4 * k4 + 1][ar] = a_r[i].y;
            As[buf][4 * k4 + 2][ar] = a_r[i].z;
            As[buf][4 * k4 + 3][ar] = a_r[i].w;
        }
        if (!BNC) {
#pragma unroll
            for (int i = 0; i < NB4; i++) {
                int k4 = bkc + i * PB;
                Bs[buf][4 * k4 + 0][bn] = b_r[i].x;
                Bs[buf][4 * k4 + 1][bn] = b_r[i].y;
                Bs[buf][4 * k4 + 2][bn] = b_r[i].z;
                Bs[buf][4 * k4 + 3][bn] = b_r[i].w;
            }
        } else {
#pragma unroll
            for (int i = 0; i < NB4; i++)
                *(float4*)&Bs[buf][bkr + 4 * i][bn4] = b_r[i];
        }
    };

    LOADA(0); LOADB(0);
    STORE(0);
    __syncthreads();

    const int nt = K / BK;
    for (int it = 0; it < nt; it++) {
        const int cur = it & 1;
        if (it + 1 < nt) { LOADA(it + 1); LOADB(it + 1); }

#pragma unroll
        for (int k = 0; k < BK; k++) {
            const float* ask = &As[cur][k][ty * TM];
            const float* bsk = &Bs[cur][k][tx];
            u64 bv[TN];
#pragma unroll
            for (int j = 0; j < TN; j++)
                bv[j] = pack2(bsk[j * NTX]);
            u64 av[NP];
#pragma unroll
            for (int p = 0; p < NP; p++)
                av[p] = *(const u64*)(ask + 2 * p);
#pragma unroll
            for (int p = 0; p < NP; p++)
#pragma unroll
                for (int j = 0; j < TN; j++)
                    ffma2(acc[p][j], av[p], bv[j]);
        }

        if (it + 1 < nt) STORE(cur ^ 1);
        __syncthreads();
    }

    float bj[TN];
#pragma unroll
    for (int j = 0; j < TN; j++)
        bj[j] = bias ? bias[n0 + j * NTX + tx] : 0.f;

#pragma unroll
    for (int p = 0; p < NP; p++) {
        int mA = m0 + ty * TM + 2 * p;
        int mB = mA + 1;
        size_t rA = (mode == 1) ? ((size_t)(mA & 63) * Tq + (mA >> 6)) : (size_t)mA;
        size_t rB = (mode == 1) ? ((size_t)(mB & 63) * Tq + (mB >> 6)) : (size_t)mB;
        float* cpa = Cb + rA * (size_t)ldc + n0;
        float* cpb = Cb + rB * (size_t)ldc + n0;
#pragma unroll
        for (int j = 0; j < TN; j++) {
            float2 f = u2f2(acc[p][j]);
            int off = j * NTX + tx;
            float va = f.x + bj[j];
            float vb = f.y + bj[j];
            if (accf) { va += cpa[off]; vb += cpb[off]; }
            cpa[off] = va;
            cpb[off] = vb;
        }
    }
}

// ============================================================================
// GRU step group: SPT steps/launch, 288 blocks x 128 threads (2 CTAs/SM so
// __syncthreads of one CTA is shadowed by the other's issue stream).
// Grid: 24 n-tiles x 12 k-splits (88x8 / 80x4, BK=8). Per-thread 8m x 8n.
// Per step: gh partial -> grid barrier -> distributed gates -> barrier.
// ============================================================================
#define SBK 8

__device__ __forceinline__ void stepbar(int* cnt, int sub, int target)
{
    __syncthreads();
    if (threadIdx.x == 0) {
        __threadfence();
        atomicAdd(cnt + sub * 32, 1);
        int s;
        do {
            s = 0;
#pragma unroll
            for (int i = 0; i < 8; i++)
                s += *(volatile int*)(cnt + i * 32);
        } while (s < target);
        __threadfence();
    }
    __syncthreads();
}

__global__ __launch_bounds__(128, 2) void gru4_k(
    const float* __restrict__ W_hh, const float* __restrict__ b_hh, int t0)
{
    __shared__ __align__(16) float As[2][SBK][64];
    __shared__ __align__(16) float Bs[2][SBK][128];

    const int tid = threadIdx.x;
    const int bx  = blockIdx.x;            // 0..23 n-tile
    const int spl = blockIdx.y;            // 0..11 k-split
    const int fbid = spl * 24 + bx;        // 0..287
    const int n0  = bx * 128;
    const int k0  = (spl < 8) ? spl * 88 : 704 + (spl - 8) * 80;
    const int nt  = (spl < 8) ? 11 : 10;   // SBK-tiles

    int* cnt = &d_cnt[t0 / SPT][0];
    const int sub = fbid & 7;

    const int ty = tid >> 4;               // 0..7  (b rows ty*8..+7)
    const int tx = tid & 15;               // n = n0 + tx + 16j

    // global load mappings (BK=8)
    const int ar  = tid & 63;              // A row (b)
    const int akc = tid >> 6;              // 0..1 (k 4-col group)
    const float* Bp = W_hh + (size_t)(n0 + tid) * Hq + k0;   // B row = tid

    const int pi = fbid * 128 + tid;       // 0..36863; active < 32768
    const int gb = pi >> 9;
    const int gj = (pi & 511) * 2;
    float2 br2, bz2, bn2;
    if (pi < Bq * (Hq / 2)) {
        br2 = *(const float2*)(b_hh + gj);
        bz2 = *(const float2*)(b_hh + Hq + gj);
        bn2 = *(const float2*)(b_hh + 2 * Hq + gj);
    }

    for (int s = 0; s < SPT; s++) {
        const int t = t0 + s;
        const float* Ht = d_H + (size_t)t * Bq * Hq;
        const float* Ap = Ht + (size_t)ar * Hq + k0 + akc * 4;

        u64 acc[4][8];
#pragma unroll
        for (int p = 0; p < 4; p++)
#pragma unroll
            for (int j = 0; j < 8; j++) acc[p][j] = 0ull;

        float4 a_r, b_r[2];
        a_r = *(const float4*)(Ap);
        b_r[0] = *(const float4*)(Bp);
        b_r[1] = *(const float4*)(Bp + 4);

        for (int it = 0; it < nt; it++) {
            const int cur = it & 1;
            // store staged regs
            As[cur][4 * akc + 0][ar] = a_r.x;
            As[cur][4 * akc + 1][ar] = a_r.y;
            As[cur][4 * akc + 2][ar] = a_r.z;
            As[cur][4 * akc + 3][ar] = a_r.w;
            Bs[cur][0][tid] = b_r[0].x;
            Bs[cur][1][tid] = b_r[0].y;
            Bs[cur][2][tid] = b_r[0].z;
            Bs[cur][3][tid] = b_r[0].w;
            Bs[cur][4][tid] = b_r[1].x;
            Bs[cur][5][tid] = b_r[1].y;
            Bs[cur][6][tid] = b_r[1].z;
            Bs[cur][7][tid] = b_r[1].w;
            __syncthreads();
            if (it + 1 < nt) {
                a_r = *(const float4*)(Ap + (it + 1) * SBK);
                b_r[0] = *(const float4*)(Bp + (it + 1) * SBK);
                b_r[1] = *(const float4*)(Bp + (it + 1) * SBK + 4);
            }
#pragma unroll
            for (int k = 0; k < SBK; k++) {
                const float* ask = &As[cur][k][ty * 8];
                const float* bsk = &Bs[cur][k][tx];
                u64 bv[8];
#pragma unroll
                for (int j = 0; j < 8; j++) bv[j] = pack2(bsk[j * 16]);
                u64 av[4];
#pragma unroll
                for (int p = 0; p < 4; p++) av[p] = *(const u64*)(ask + 2 * p);
#pragma unroll
                for (int p = 0; p < 4; p++)
#pragma unroll
                    for (int j = 0; j < 8; j++)
                        ffma2(acc[p][j], av[p], bv[j]);
            }
            __syncthreads();
        }

        // write partials d_ghp[spl][b][n0+...]
#pragma unroll
        for (int p = 0; p < 4; p++) {
            int bA = ty * 8 + 2 * p;
            float* cpa = &d_ghp[spl][bA][n0];
            float* cpb = &d_ghp[spl][bA + 1][n0];
#pragma unroll
            for (int j = 0; j < 8; j++) {
                float2 f = u2f2(acc[p][j]);
                int off = j * 16 + tx;
                cpa[off] = f.x;
                cpb[off] = f.y;
            }
        }

        stepbar(cnt, sub, NBGRU * (2 * s + 1));

        // ---- distributed gates: one float2 pair per thread ----
        if (pi < Bq * (Hq / 2)) {
            float2 sr = br2, sz = bz2, sn = bn2;
#pragma unroll
            for (int sp = 0; sp < NSPL; sp++) {
                const float* q = &d_ghp[sp][gb][0];
                float2 v;
                v = __ldcg((const float2*)(q + gj));           sr.x += v.x; sr.y += v.y;
                v = __ldcg((const float2*)(q + Hq + gj));      sz.x += v.x; sz.y += v.y;
                v = __ldcg((const float2*)(q + 2 * Hq + gj));  sn.x += v.x; sn.y += v.y;
            }
            const float* gib = d_gi + ((size_t)t * Bq + gb) * G3q;
            float2 gir = *(const float2*)(gib + gj);
            float2 giz = *(const float2*)(gib + Hq + gj);
            float2 gin = *(const float2*)(gib + 2 * Hq + gj);
            float2 hp  = __ldcg((const float2*)(Ht + (size_t)gb * Hq + gj));

            float rx = 1.f / (1.f + expf(-(gir.x + sr.x)));
            float ry = 1.f / (1.f + expf(-(gir.y + sr.y)));
            float zx = 1.f / (1.f + expf(-(giz.x + sz.x)));
            float zy = 1.f / (1.f + expf(-(giz.y + sz.y)));
            float nx = tanhf(gin.x + rx * sn.x);
            float ny = tanhf(gin.y + ry * sn.y);
            float2 hn;
            hn.x = (1.f - zx) * nx + zx * hp.x;
            hn.y = (1.f - zy) * ny + zy * hp.y;
            *(float2*)(d_H + ((size_t)(t + 1) * Bq + gb) * Hq + gj) = hn;
        }

        stepbar(cnt, sub, NBGRU * (2 * s + 2));
    }
}

// ---------------- small kernels ----------------------------------------------
__global__ void embed_k(const int* __restrict__ targets, const float* __restrict__ E)
{
    int m = blockIdx.x;
    int t = m >> 6, b = m & 63;
    int id = (t == 0) ? 0 : targets[b * Tq + (t - 1)];
    const float4* src = (const float4*)(E + (size_t)id * WEq);
    float4* dst = (float4*)(d_X + (size_t)m * WEq);
    dst[threadIdx.x] = src[threadIdx.x];
}

__global__ void words_k(const unsigned char* __restrict__ mask8)
{
    int b = blockIdx.x, t = threadIdx.x;
    int is8 = (mask8[1] != 0);
    int v;
    if (is8) v = mask8[b * Tq + t] ? 1 : 0;
    else     v = ((const int*)mask8)[b * Tq + t] ? 1 : 0;
#pragma unroll
    for (int o = 16; o; o >>= 1) v += __shfl_down_sync(0xffffffffu, v, o);
    __shared__ int red[8];
    if ((t & 31) == 0) red[t >> 5] = v;
    __syncthreads();
    if (t == 0) {
        int s = 0;
#pragma unroll
        for (int i = 0; i < 8; i++) s += red[i];
        d_words[b] = s;
    }
}

__global__ void h0_k(const float* __restrict__ enc)
{
    int b = blockIdx.x;
    const float4* src = (const float4*)(enc + ((size_t)b * Tq + (Tq - 1)) * Hq);
    float4* dst = (float4*)(d_H + (size_t)b * Hq);
    dst[threadIdx.x] = src[threadIdx.x];
}

__global__ void softmax_k()
{
    int m = blockIdx.x;
    int b = m & (Bq - 1);
    int wn = d_words[b];
    float* e = d_e + (size_t)m * Tq;
    int s = threadIdx.x;
    float v = (s < wn) ? e[s] : -3.0e38f;

    __shared__ float red[8];
    __shared__ float smax, ssum;
    float mx = v;
#pragma unroll
    for (int o = 16; o; o >>= 1) mx = fmaxf(mx, __shfl_xor_sync(0xffffffffu, mx, o));
    if ((s & 31) == 0) red[s >> 5] = mx;
    __syncthreads();
    if (s == 0) {
        float x = red[0];
#pragma unroll
        for (int i = 1; i < 8; i++) x = fmaxf(x, red[i]);
        smax = x;
    }
    __syncthreads();
    float ex = (s < wn) ? expf(v - smax) : 0.f;
    float sum = ex;
#pragma unroll
    for (int o = 16; o; o >>= 1) sum += __shfl_xor_sync(0xffffffffu, sum, o);
    if ((s & 31) == 0) red[s >> 5] = sum;
    __syncthreads();
    if (s == 0) {
        float x = 0.f;
#pragma unroll
        for (int i = 0; i < 8; i++) x += red[i];
        ssum = 1.f / x;
    }
    __syncthreads();
    e[s] = ex * ssum;
}

// ---------------- launch ------------------------------------------------------
extern "C" void kernel_launch(void* const* d_in, const int* in_sizes, int n_in,
                              void* d_out, int out_size)
{
    const float*         enc     = (const float*)d_in[0];
    const unsigned char* mask    = (const unsigned char*)d_in[1];
    const int*           targets = (const int*)d_in[2];
    const float*         E       = (const float*)d_in[3];
    const float*         W_ih    = (const float*)d_in[4];
    const float*         W_hh    = (const float*)d_in[5];
    const float*         b_ih    = (const float*)d_in[6];
    const float*         b_hh    = (const float*)d_in[7];
    const float*         W_out   = (const float*)d_in[8];
    const float*         b_out   = (const float*)d_in[9];
    float* out = (float*)d_out;

    void* p;
    cudaGetSymbolAddress(&p, d_X);   float* X   = (float*)p;
    cudaGetSymbolAddress(&p, d_gi);  float* GI  = (float*)p;
    cudaGetSymbolAddress(&p, d_H);   float* Hh  = (float*)p;
    cudaGetSymbolAddress(&p, d_e);   float* Ee  = (float*)p;
    cudaGetSymbolAddress(&p, d_ctx); float* CTX = (float*)p;
    void* cntp;
    cudaGetSymbolAddress(&cntp, d_cnt);

    // Phase 0
    cudaMemsetAsync(cntp, 0, (Tq / SPT) * 8 * 32 * sizeof(int));
    embed_k<<<Tq * Bq, 64>>>(targets, E);
    words_k<<<Bq, 256>>>(mask);
    h0_k<<<Bq, 256>>>(enc);

    // Phase 1: gi = X @ W_ih^T + b_ih   (16384 x 3072 x 256), layout [t][b][n]
    gemm2_k<128, 128, 16, 8, false><<<dim3(G3q / 128, (Tq * Bq) / 128, 1), 128>>>(
        X, nullptr, 1 << 30, W_ih, GI, WEq, WEq, WEq, G3q, 0, 0, 0, b_ih, 0, 0);

    // Phase 2: GRU recurrence — SPT steps/launch, 288-block step kernel
    for (int t0 = 0; t0 < Tq; t0 += SPT)
        gru4_k<<<dim3(24, NSPL), 128>>>(W_hh, b_hh, t0);

    // Phase 3a: e[t,b,s] = h1[t,b,:] . enc[b,s,:]
    gemm2_k<128, 128, 16, 8, false><<<dim3(Tq / 128, Tq / 128, Bq), 128>>>(
        Hh + (size_t)Bq * Hq, nullptr, 1 << 30, enc, Ee, Hq,
        Bq * Hq, Hq, Bq * Tq,
        Hq, (long long)Tq * Hq, Tq,
        nullptr, 0, 0);

    // Phase 3b: masked softmax
    softmax_k<<<Tq * Bq, Tq>>>();

    // Phase 3c: ctx[t,b,:] = alpha[t,b,:] @ enc[b]   (B n-contiguous)
    gemm2_k<128, 128, 16, 8, true><<<dim3(Hq / 128, Tq / 128, Bq), 128>>>(
        Ee, nullptr, 1 << 30, enc, CTX, Tq,
        Bq * Tq, Hq, Bq * Hq,
        Tq, (long long)Tq * Hq, Hq,
        nullptr, 0, 0);

    // Phase 4: logits = [h1 | ctx] @ W_out^T + b_out, concat K=2048, (B,T,C) out
    gemm2_k<128, 128, 16, 8, false><<<dim3(Cq / 128, (Tq * Bq) / 128, 1), 128>>>(
        Hh + (size_t)Bq * Hq, CTX, Hq, W_out, out, 2 * Hq,
        Hq, 2 * Hq, Cq, 0, 0, 0, b_out, 0, 1);
}